// round 11
// baseline (speedup 1.0000x reference)
#include <cuda_runtime.h>
#include <cstdint>

// ===========================================================================
// TreeLSTMCell via legacy tensor-core path (mma.sync.m16n8k8.tf32).
// Toolchain targets plain sm_103 -> no tcgen05/TMA-a features; mma.sync,
// cp.async and cvt.rna.tf32 are family-generic and compile.
//
// CTA = 128 nodes, 256 threads, warp grid 2(M)x4(N), warp tile 64x32.
// Five GEMM passes over N-windows of 128:
//   P0: f(child0) = h_cat @ Uf[:,0:128]    K=256  -> out_c = sig(f0)*c_ch0
//   P1: f(child1) = h_cat @ Uf[:,128:256]  K=256  -> out_c += sig(f1)*c_ch1
//   P2: u = maskedA @ Wcomb[:,256:384]     K=384  -> out_h = tanh(u+b)
//   P3: i = maskedA @ Wcomb[:,0:128]       K=384  -> out_c = sig(i+b)*out_h + out_c
//   P4: o = maskedA @ Wcomb[:,128:256]     K=384  -> out_h = sig(o+b)*tanh(out_c)
// maskedA row = leaf ? [0,0,x] : [h_ch0,h_ch1,0]; Wcomb = [U_iou | W_iou]
// (pre-rounded to tf32 by prep kernel into __device__ scratch).
// Inter-pass scalars ride in d_out; each lane re-reads its own addresses.
// ===========================================================================

#define HH   128
#define KC   32          // K per smem chunk
#define PADK 36          // padded row stride (floats); 36%32==4 -> LDS conflict-free
#define SLOT 18432       // 128*36*4 bytes per chunk buffer
#define A0_OFF   0
#define B0_OFF   (2*SLOT)
#define META_OFF (4*SLOT)
#define SMEM_BYTES (META_OFF + 5632)

__device__ float g_Wf[256 * 256];     // Uf, tf32-rounded, row-major [o][k]
__device__ float g_Wiou[384 * 384];   // [U_iou | W_iou] combined, tf32-rounded

__device__ __forceinline__ uint32_t cvt_tf32(float f) {
    uint32_t r;
    asm("cvt.rna.tf32.f32 %0, %1;" : "=r"(r) : "f"(f));
    return r;
}

__global__ void prep_kernel(const float* __restrict__ Uf,
                            const float* __restrict__ Uiou,
                            const float* __restrict__ Wiou) {
    int i = blockIdx.x * blockDim.x + threadIdx.x;
    if (i < 256 * 256) g_Wf[i] = __uint_as_float(cvt_tf32(Uf[i]));
    int j = i - 256 * 256;
    if (j >= 0 && j < 384 * 384) {
        int o = j / 384, k = j - o * 384;
        float v = (k < 256) ? Uiou[o * 256 + k] : Wiou[o * 128 + (k - 256)];
        g_Wiou[j] = __uint_as_float(cvt_tf32(v));
    }
}

__device__ __forceinline__ uint32_t smem_u32(const void* p) {
    uint32_t a;
    asm("{ .reg .u64 t; cvta.to.shared.u64 t, %1; cvt.u32.u64 %0, t; }"
        : "=r"(a) : "l"(p));
    return a;
}
__device__ __forceinline__ void cpa16(uint32_t dst, const void* src, int sz) {
    asm volatile("cp.async.ca.shared.global [%0], [%1], 16, %2;"
                 :: "r"(dst), "l"(src), "r"(sz) : "memory");
}
#define CP_COMMIT() asm volatile("cp.async.commit_group;" ::: "memory")
#define CP_WAIT0()  asm volatile("cp.async.wait_group 0;" ::: "memory")

__device__ __forceinline__ void mma8(float d[4], const uint32_t a[4],
                                     const uint32_t b[2]) {
    asm volatile(
        "mma.sync.aligned.m16n8k8.row.col.f32.tf32.tf32.f32 "
        "{%0,%1,%2,%3}, {%4,%5,%6,%7}, {%8,%9}, {%0,%1,%2,%3};"
        : "+f"(d[0]), "+f"(d[1]), "+f"(d[2]), "+f"(d[3])
        : "r"(a[0]), "r"(a[1]), "r"(a[2]), "r"(a[3]), "r"(b[0]), "r"(b[1]));
}
__device__ __forceinline__ float sigm(float v) { return 1.0f / (1.0f + __expf(-v)); }

// ---- chunk loaders (cp.async, 4 x 16B per thread each) ----
// TYPE 0: unmasked h_cat (F passes).  TYPE 1: masked [h_cat | x] (IOU passes).
template <int TYPE>
__device__ __forceinline__ void loadA(char* dst, int kc,
                                      const float* __restrict__ h,
                                      const float* __restrict__ x,
                                      const int* sCh, const int* sLf,
                                      int base, int tid) {
#pragma unroll
    for (int r = 0; r < 4; r++) {
        int idx = tid + r * 256;
        int m = idx >> 3, s = idx & 7;
        int k = kc * KC + s * 4;
        uint32_t d = smem_u32(dst + (m * PADK + s * 4) * 4);
        const float* src;
        int sz = 16;
        if (TYPE == 0) {
            src = h + (size_t)sCh[2 * m + (k >> 7)] * HH + (k & 127);
        } else {
            int leaf = sLf[m];
            if (k < 256) {
                src = h + (size_t)sCh[2 * m + (k >> 7)] * HH + (k & 127);
                sz = leaf ? 0 : 16;     // zfill leaf rows
            } else {
                src = x + (size_t)(base + m) * HH + (k & 127);
                sz = leaf ? 16 : 0;     // zfill internal rows
            }
        }
        cpa16(d, src, sz);
    }
}

__device__ __forceinline__ void loadB(const float* __restrict__ W, int ldw,
                                      int nb, char* dst, int kc, int tid) {
#pragma unroll
    for (int r = 0; r < 4; r++) {
        int idx = tid + r * 256;
        int n = idx >> 3, s = idx & 7;
        cpa16(smem_u32(dst + (n * PADK + s * 4) * 4),
              W + (size_t)(nb + n) * ldw + kc * KC + s * 4, 16);
    }
}

// ---- one K=32 chunk of warp-tile mma (64 HMMA / warp) ----
__device__ __forceinline__ void compute_chunk(const float* sA, const float* sB,
                                              float acc[4][4][4],
                                              int wm, int wn, int g, int t) {
#pragma unroll
    for (int kk = 0; kk < 4; kk++) {
        uint32_t af[4][4];
#pragma unroll
        for (int mt = 0; mt < 4; mt++) {
            const float* ap = sA + (wm * 64 + mt * 16 + g) * PADK + kk * 8 + t;
            af[mt][0] = cvt_tf32(ap[0]);
            af[mt][1] = cvt_tf32(ap[8 * PADK]);
            af[mt][2] = cvt_tf32(ap[4]);
            af[mt][3] = cvt_tf32(ap[8 * PADK + 4]);
        }
        uint32_t bf[4][2];
#pragma unroll
        for (int nt = 0; nt < 4; nt++) {
            const float* bp = sB + (wn * 32 + nt * 8 + g) * PADK + kk * 8 + t;
            bf[nt][0] = __float_as_uint(bp[0]);
            bf[nt][1] = __float_as_uint(bp[4]);
        }
#pragma unroll
        for (int mt = 0; mt < 4; mt++)
#pragma unroll
            for (int nt = 0; nt < 4; nt++)
                mma8(acc[mt][nt], af[mt], bf[nt]);
    }
}

// ---- per-pass epilogue; lane owns (row,col) = same mapping every pass ----
template <int PASS>
__device__ __forceinline__ void epilogue(float acc[4][4][4],
                                         const float* __restrict__ c,
                                         const int* sCh, const int* sLf,
                                         const float* sbUf, const float* sbI,
                                         const float* sbW,
                                         float* __restrict__ outH,
                                         float* __restrict__ outC,
                                         int base, int wm, int wn, int g, int t) {
#pragma unroll
    for (int mt = 0; mt < 4; mt++) {
#pragma unroll
        for (int hr = 0; hr < 2; hr++) {
            int row = wm * 64 + mt * 16 + hr * 8 + g;
            size_t node = (size_t)(base + row);
            const float* bb = sLf[row] ? sbW : sbI;
            const float* crow = c;  // only used in P0/P1
            if (PASS == 0) crow = c + (size_t)sCh[2 * row] * HH;
            if (PASS == 1) crow = c + (size_t)sCh[2 * row + 1] * HH;
#pragma unroll
            for (int nt = 0; nt < 4; nt++) {
                int col = wn * 32 + nt * 8 + 2 * t;
                float v0 = acc[mt][nt][hr * 2 + 0];
                float v1 = acc[mt][nt][hr * 2 + 1];
                if (PASS == 0) {
                    float2 cc = *(const float2*)(crow + col);
                    float2 r = make_float2(sigm(v0 + sbUf[col]) * cc.x,
                                           sigm(v1 + sbUf[col + 1]) * cc.y);
                    *(float2*)(outC + node * HH + col) = r;
                } else if (PASS == 1) {
                    float2 cc = *(const float2*)(crow + col);
                    float2 old = *(const float2*)(outC + node * HH + col);
                    float2 r = make_float2(
                        old.x + sigm(v0 + sbUf[128 + col]) * cc.x,
                        old.y + sigm(v1 + sbUf[128 + col + 1]) * cc.y);
                    *(float2*)(outC + node * HH + col) = r;
                } else if (PASS == 2) {
                    float2 r = make_float2(tanhf(v0 + bb[256 + col]),
                                           tanhf(v1 + bb[256 + col + 1]));
                    *(float2*)(outH + node * HH + col) = r;
                } else if (PASS == 3) {
                    float2 tu = *(const float2*)(outH + node * HH + col);
                    float2 cf = *(const float2*)(outC + node * HH + col);
                    float2 r = make_float2(sigm(v0 + bb[col]) * tu.x + cf.x,
                                           sigm(v1 + bb[col + 1]) * tu.y + cf.y);
                    *(float2*)(outC + node * HH + col) = r;
                } else {
                    float2 cn = *(const float2*)(outC + node * HH + col);
                    float2 r = make_float2(
                        sigm(v0 + bb[128 + col]) * tanhf(cn.x),
                        sigm(v1 + bb[128 + col + 1]) * tanhf(cn.y));
                    *(float2*)(outH + node * HH + col) = r;
                }
            }
        }
    }
}

template <int PASS, int ATYPE, int NK>
__device__ __forceinline__ void run_pass(char* smem,
                                         const float* __restrict__ W, int ldw, int nb,
                                         const float* __restrict__ h,
                                         const float* __restrict__ x,
                                         const float* __restrict__ c,
                                         const int* sCh, const int* sLf,
                                         const float* sbUf, const float* sbI,
                                         const float* sbW,
                                         float* outH, float* outC, int base,
                                         int tid, int wm, int wn, int g, int t) {
    float acc[4][4][4];
#pragma unroll
    for (int a1 = 0; a1 < 4; a1++)
#pragma unroll
        for (int a2 = 0; a2 < 4; a2++)
#pragma unroll
            for (int a3 = 0; a3 < 4; a3++) acc[a1][a2][a3] = 0.f;

    loadA<ATYPE>(smem + A0_OFF, 0, h, x, sCh, sLf, base, tid);
    loadB(W, ldw, nb, smem + B0_OFF, 0, tid);
    CP_COMMIT();
#pragma unroll 1
    for (int kc = 0; kc < NK; kc++) {
        CP_WAIT0();
        __syncthreads();   // chunk kc visible to all; all warps past chunk kc-1
        if (kc + 1 < NK) {
            loadA<ATYPE>(smem + A0_OFF + ((kc + 1) & 1) * SLOT, kc + 1,
                         h, x, sCh, sLf, base, tid);
            loadB(W, ldw, nb, smem + B0_OFF + ((kc + 1) & 1) * SLOT, kc + 1, tid);
            CP_COMMIT();   // load of kc+1 overlaps compute of kc
        }
        compute_chunk((const float*)(smem + A0_OFF + (kc & 1) * SLOT),
                      (const float*)(smem + B0_OFF + (kc & 1) * SLOT),
                      acc, wm, wn, g, t);
    }
    epilogue<PASS>(acc, c, sCh, sLf, sbUf, sbI, sbW, outH, outC,
                   base, wm, wn, g, t);
}

__global__ void __launch_bounds__(256, 2)
tree_kernel(const float* __restrict__ x, const float* __restrict__ h,
            const float* __restrict__ c, const int* __restrict__ children,
            const int* __restrict__ is_leaf,
            const float* __restrict__ bWiou, const float* __restrict__ bUiou,
            const float* __restrict__ bUf,
            float* __restrict__ out, int N) {
    extern __shared__ char smem[];
    int*   sCh  = (int*)(smem + META_OFF);          // 256 i32
    int*   sLf  = (int*)(smem + META_OFF + 1024);   // 128 i32
    float* sbUf = (float*)(smem + META_OFF + 1536); // 256 f
    float* sbI  = (float*)(smem + META_OFF + 2560); // 384 f
    float* sbW  = (float*)(smem + META_OFF + 4096); // 384 f

    const int tid = threadIdx.x;
    const int wid = tid >> 5, lane = tid & 31;
    const int g = lane >> 2, t = lane & 3;
    const int wm = wid >> 2, wn = wid & 3;
    const int base = blockIdx.x * 128;

    sCh[tid] = children[base * 2 + tid];
    sbUf[tid] = bUf[tid];
    sbI[tid] = bUiou[tid];
    sbW[tid] = bWiou[tid];
    if (tid < 128) {
        sLf[tid] = is_leaf[base + tid];
        sbI[256 + tid] = bUiou[256 + tid];
        sbW[256 + tid] = bWiou[256 + tid];
    }
    __syncthreads();

    float* outH = out;
    float* outC = out + (size_t)N * HH;

    run_pass<0, 0, 8>(smem, g_Wf, 256, 0, h, x, c, sCh, sLf, sbUf, sbI, sbW,
                      outH, outC, base, tid, wm, wn, g, t);
    run_pass<1, 0, 8>(smem, g_Wf, 256, 128, h, x, c, sCh, sLf, sbUf, sbI, sbW,
                      outH, outC, base, tid, wm, wn, g, t);
    run_pass<2, 1, 12>(smem, g_Wiou, 384, 256, h, x, c, sCh, sLf, sbUf, sbI, sbW,
                       outH, outC, base, tid, wm, wn, g, t);
    run_pass<3, 1, 12>(smem, g_Wiou, 384, 0, h, x, c, sCh, sLf, sbUf, sbI, sbW,
                       outH, outC, base, tid, wm, wn, g, t);
    run_pass<4, 1, 12>(smem, g_Wiou, 384, 128, h, x, c, sCh, sLf, sbUf, sbI, sbW,
                       outH, outC, base, tid, wm, wn, g, t);
}

extern "C" void kernel_launch(void* const* d_in, const int* in_sizes, int n_in,
                              void* d_out, int out_size) {
    const float* x        = (const float*)d_in[0];
    const float* h        = (const float*)d_in[1];
    const float* c        = (const float*)d_in[2];
    const int*   children = (const int*)d_in[3];
    const int*   is_leaf  = (const int*)d_in[4];
    const float* W_iou    = (const float*)d_in[5];
    const float* b_Wiou   = (const float*)d_in[6];
    const float* U_iou    = (const float*)d_in[7];
    const float* b_Uiou   = (const float*)d_in[8];
    const float* U_f      = (const float*)d_in[9];
    const float* b_Uf     = (const float*)d_in[10];

    int N = in_sizes[1] / HH;   // 400000, multiple of 128

    cudaFuncSetAttribute(tree_kernel,
                         cudaFuncAttributeMaxDynamicSharedMemorySize, SMEM_BYTES);

    prep_kernel<<<(256 * 256 + 384 * 384 + 255) / 256, 256>>>(U_f, U_iou, W_iou);
    tree_kernel<<<N / 128, 256, SMEM_BYTES>>>(x, h, c, children, is_leaf,
                                              b_Wiou, b_Uiou, b_Uf,
                                              (float*)d_out, N);
}